// round 1
// baseline (speedup 1.0000x reference)
#include <cuda_runtime.h>
#include <cuda_bf16.h>

// Problem constants (SpectralClassifier: B=1024, S=128, D=768)
#define BB 1024
#define SS 128
#define DD 768
#define NSEQ 127          // positions 1..127
#define H1 256
#define H2 64
#define OUTC 2
#define ROWS 8            // rows per block in MLP kernel

// Scratch (no cudaMalloc allowed)
__device__ float g_v[BB * DD];
__device__ int g_mask_mode;   // 0=int32, 1=float32, 2=uint8

// ---------------------------------------------------------------------------
// Detect attention_mask storage dtype from bit patterns.
// int32 0/1  -> every 4-byte word is 0 or 1
// float 0/1  -> every word is 0x0 or 0x3F800000
// uint8 0/1  -> words are packed byte patterns (neither of the above)
// ---------------------------------------------------------------------------
__global__ void detect_mask_kernel(const void* __restrict__ mask, int n_elems) {
    __shared__ int s_not_int01;
    __shared__ int s_not_f01;
    if (threadIdx.x == 0) { s_not_int01 = 0; s_not_f01 = 0; }
    __syncthreads();
    const unsigned int* w = (const unsigned int*)mask;
    int nwords = n_elems >> 2;   // safe for all candidate dtypes
    int bad_i = 0, bad_f = 0;
    for (int i = threadIdx.x; i < nwords; i += blockDim.x) {
        unsigned int vv = w[i];
        if (vv > 1u) bad_i = 1;
        float f = __uint_as_float(vv);
        if (!(f == 0.0f || f == 1.0f)) bad_f = 1;
    }
    if (bad_i) atomicOr(&s_not_int01, 1);
    if (bad_f) atomicOr(&s_not_f01, 1);
    __syncthreads();
    if (threadIdx.x == 0) {
        int mode;
        if (!s_not_int01)      mode = 0;
        else if (!s_not_f01)   mode = 1;
        else                   mode = 2;
        g_mask_mode = mode;
    }
}

__device__ __forceinline__ bool mask_at(const void* mask, int idx, int mode) {
    if (mode == 0) return ((const int*)mask)[idx] != 0;
    if (mode == 1) return ((const float*)mask)[idx] != 0.0f;
    return ((const unsigned char*)mask)[idx] != 0;
}

// ---------------------------------------------------------------------------
// Kernel A: v[b,d] = (1/127) * sum_{s=1..127, mask[b,s]} hidden[b,s,d]
// One block per b. 192 threads, each owns one float4 of the 768-wide row.
// Masked-off rows are never fetched (saves ~50% DRAM traffic).
// ---------------------------------------------------------------------------
__global__ void __launch_bounds__(192) reduce_kernel(
    const float* __restrict__ hidden, const void* __restrict__ mask)
{
    __shared__ int s_idx[SS];
    __shared__ int s_cnt;
    __shared__ unsigned char s_m[SS];

    const int b   = blockIdx.x;
    const int tid = threadIdx.x;
    const int mode = g_mask_mode;

    if (tid < SS) {
        s_m[tid] = (unsigned char)mask_at(mask, b * SS + tid, mode);
    }
    __syncthreads();
    if (tid == 0) {
        int c = 0;
        for (int s = 1; s < SS; s++) if (s_m[s]) s_idx[c++] = s;
        s_cnt = c;
    }
    __syncthreads();

    const int cnt = s_cnt;
    const float4* hp = (const float4*)(hidden + (size_t)b * SS * DD);

    float4 a0 = make_float4(0.f, 0.f, 0.f, 0.f);
    float4 a1 = make_float4(0.f, 0.f, 0.f, 0.f);
    float4 a2 = make_float4(0.f, 0.f, 0.f, 0.f);
    float4 a3 = make_float4(0.f, 0.f, 0.f, 0.f);

    int i = 0;
    for (; i + 4 <= cnt; i += 4) {
        int q0 = s_idx[i], q1 = s_idx[i + 1], q2 = s_idx[i + 2], q3 = s_idx[i + 3];
        float4 x0 = __ldg(&hp[q0 * (DD / 4) + tid]);
        float4 x1 = __ldg(&hp[q1 * (DD / 4) + tid]);
        float4 x2 = __ldg(&hp[q2 * (DD / 4) + tid]);
        float4 x3 = __ldg(&hp[q3 * (DD / 4) + tid]);
        a0.x += x0.x; a0.y += x0.y; a0.z += x0.z; a0.w += x0.w;
        a1.x += x1.x; a1.y += x1.y; a1.z += x1.z; a1.w += x1.w;
        a2.x += x2.x; a2.y += x2.y; a2.z += x2.z; a2.w += x2.w;
        a3.x += x3.x; a3.y += x3.y; a3.z += x3.z; a3.w += x3.w;
    }
    for (; i < cnt; i++) {
        float4 x0 = __ldg(&hp[s_idx[i] * (DD / 4) + tid]);
        a0.x += x0.x; a0.y += x0.y; a0.z += x0.z; a0.w += x0.w;
    }

    const float inv = 1.0f / 127.0f;
    float4 r;
    r.x = (a0.x + a1.x + a2.x + a3.x) * inv;
    r.y = (a0.y + a1.y + a2.y + a3.y) * inv;
    r.z = (a0.z + a1.z + a2.z + a3.z) * inv;
    r.w = (a0.w + a1.w + a2.w + a3.w) * inv;
    ((float4*)(g_v + (size_t)b * DD))[tid] = r;
}

// ---------------------------------------------------------------------------
// Kernel B: full MLP per 8-row block.
//   h1 = relu(v @ W1 + b1)   [8 x 256]  (main FFMA loop, K=768)
//   h2 = relu(h1 @ W2 + b2)  [8 x 64]
//   out = h2 @ W3 + b3       [8 x 2]
// 128 blocks x 256 threads. Thread tid owns column tid of h1 for all 8 rows.
// ---------------------------------------------------------------------------
__global__ void __launch_bounds__(256) mlp_kernel(
    const float* __restrict__ W1, const float* __restrict__ b1,
    const float* __restrict__ W2, const float* __restrict__ b2,
    const float* __restrict__ W3, const float* __restrict__ b3,
    float* __restrict__ out)
{
    __shared__ float vs[DD * ROWS];       // [k][r], r fast -> LDS.128 broadcast
    __shared__ float h1s[ROWS][H1];
    __shared__ float h2s[ROWS][H2];

    const int tid = threadIdx.x;
    const int r0  = blockIdx.x * ROWS;

    // Stage v rows into shared: vs[k*8 + r]
    #pragma unroll
    for (int r = 0; r < ROWS; r++) {
        const float* src = g_v + (size_t)(r0 + r) * DD;
        for (int k = tid; k < DD; k += 256) {
            vs[k * ROWS + r] = src[k];
        }
    }
    __syncthreads();

    // GEMM1: acc[r] = sum_k v[r][k] * W1[k][tid]
    float acc[ROWS];
    #pragma unroll
    for (int r = 0; r < ROWS; r++) acc[r] = 0.0f;

    const float* w1c = W1 + tid;
    #pragma unroll 4
    for (int k = 0; k < DD; k++) {
        float w = __ldg(w1c + k * H1);
        float4 va = *(const float4*)&vs[k * ROWS];
        float4 vb = *(const float4*)&vs[k * ROWS + 4];
        acc[0] = fmaf(va.x, w, acc[0]);
        acc[1] = fmaf(va.y, w, acc[1]);
        acc[2] = fmaf(va.z, w, acc[2]);
        acc[3] = fmaf(va.w, w, acc[3]);
        acc[4] = fmaf(vb.x, w, acc[4]);
        acc[5] = fmaf(vb.y, w, acc[5]);
        acc[6] = fmaf(vb.z, w, acc[6]);
        acc[7] = fmaf(vb.w, w, acc[7]);
    }
    {
        float bias = __ldg(&b1[tid]);
        #pragma unroll
        for (int r = 0; r < ROWS; r++) {
            h1s[r][tid] = fmaxf(acc[r] + bias, 0.0f);
        }
    }
    __syncthreads();

    // GEMM2: thread t -> col j = t&63, rows rr and rr+4 where rr = t>>6
    {
        const int j  = tid & (H2 - 1);
        const int rr = tid >> 6;           // 0..3
        float s0 = 0.0f, s1 = 0.0f;
        #pragma unroll 4
        for (int k = 0; k < H1; k++) {
            float w = __ldg(&W2[k * H2 + j]);
            s0 = fmaf(h1s[rr][k],     w, s0);
            s1 = fmaf(h1s[rr + 4][k], w, s1);
        }
        float bias = __ldg(&b2[j]);
        h2s[rr][j]     = fmaxf(s0 + bias, 0.0f);
        h2s[rr + 4][j] = fmaxf(s1 + bias, 0.0f);
    }
    __syncthreads();

    // GEMM3: 16 outputs (8 rows x 2 logits)
    if (tid < ROWS * OUTC) {
        const int r = tid >> 1;
        const int j = tid & 1;
        float s = __ldg(&b3[j]);
        #pragma unroll 8
        for (int c = 0; c < H2; c++) {
            s = fmaf(h2s[r][c], __ldg(&W3[c * OUTC + j]), s);
        }
        out[(size_t)(r0 + r) * OUTC + j] = s;
    }
}

// ---------------------------------------------------------------------------
extern "C" void kernel_launch(void* const* d_in, const int* in_sizes, int n_in,
                              void* d_out, int out_size) {
    const float* hidden = (const float*)d_in[0];
    const void*  mask   = d_in[1];
    const float* W1 = (const float*)d_in[2];
    const float* b1 = (const float*)d_in[3];
    const float* W2 = (const float*)d_in[4];
    const float* b2 = (const float*)d_in[5];
    const float* W3 = (const float*)d_in[6];
    const float* b3 = (const float*)d_in[7];
    float* out = (float*)d_out;

    detect_mask_kernel<<<1, 256>>>(mask, BB * SS);
    reduce_kernel<<<BB, 192>>>(hidden, mask);
    mlp_kernel<<<BB / ROWS, 256>>>(W1, b1, W2, b2, W3, b3, out);
}

// round 2
// speedup vs baseline: 2.4676x; 2.4676x over previous
#include <cuda_runtime.h>
#include <cuda_bf16.h>

// Problem constants (SpectralClassifier: B=1024, S=128, D=768)
#define BB 1024
#define SS 128
#define DD 768
#define H1 256
#define H2 64
#define OUTC 2
#define ROWS 8
#define DET_WORDS 4096   // sample size for dtype detection (16KB)

// Scratch (no cudaMalloc allowed).
// g_vp holds UNSCALED partial sums: [half][b][d], half in {0,1}
__device__ float g_vp[2 * BB * DD];
__device__ int g_mask_mode;   // 0=int32, 1=float32, 2=uint8

// ---------------------------------------------------------------------------
// Detect attention_mask storage dtype from a 4096-word sample.
// int32 0/1  -> every word is 0 or 1
// float 0/1  -> every word is 0x0 or 0x3F800000
// uint8 0/1  -> packed byte patterns (neither of the above)
// Random ~50% mask guarantees nonzero words in the sample.
// ---------------------------------------------------------------------------
__global__ void detect_mask_kernel(const unsigned int* __restrict__ w) {
    __shared__ int s_bad_i, s_bad_f;
    if (threadIdx.x == 0) { s_bad_i = 0; s_bad_f = 0; }
    __syncthreads();
    int bad_i = 0, bad_f = 0;
    const uint4* w4 = (const uint4*)w;
    for (int i = threadIdx.x; i < DET_WORDS / 4; i += blockDim.x) {
        uint4 v = __ldg(&w4[i]);
        unsigned arr[4] = {v.x, v.y, v.z, v.w};
        #pragma unroll
        for (int j = 0; j < 4; j++) {
            unsigned u = arr[j];
            if (u > 1u) bad_i = 1;
            float f = __uint_as_float(u);
            if (!(f == 0.0f || f == 1.0f)) bad_f = 1;
        }
    }
    if (bad_i) atomicOr(&s_bad_i, 1);
    if (bad_f) atomicOr(&s_bad_f, 1);
    __syncthreads();
    if (threadIdx.x == 0) {
        g_mask_mode = (!s_bad_i) ? 0 : ((!s_bad_f) ? 1 : 2);
    }
}

__device__ __forceinline__ bool mask_at(const void* mask, int idx, int mode) {
    if (mode == 0) return ((const int*)mask)[idx] != 0;
    if (mode == 1) return ((const float*)mask)[idx] != 0.0f;
    return ((const unsigned char*)mask)[idx] != 0;
}

// ---------------------------------------------------------------------------
// Kernel A: partial masked seq-sums.
// 2048 blocks: blockIdx.x = b*2 + half. half 0 covers s in [1,64),
// half 1 covers s in [64,128). 192 threads, one float4 column each.
// Ballot compaction + 8-deep LDG pipeline. Unscaled partials -> g_vp.
// ---------------------------------------------------------------------------
__global__ void __launch_bounds__(192) reduce_kernel(
    const float* __restrict__ hidden, const void* __restrict__ mask)
{
    __shared__ int s_idx[64];
    __shared__ int s_cnt;
    __shared__ unsigned s_bal[2];
    __shared__ int s_wc[2];

    const int b     = blockIdx.x >> 1;
    const int half  = blockIdx.x & 1;
    const int lo    = half ? 64 : 1;
    const int nrows = half ? 64 : 63;
    const int tid   = threadIdx.x;
    const int mode  = g_mask_mode;

    bool m = false;
    if (tid < 64) {
        m = (tid < nrows) && mask_at(mask, b * SS + lo + tid, mode);
        unsigned bal = __ballot_sync(0xffffffffu, m);
        if ((tid & 31) == 0) { s_bal[tid >> 5] = bal; s_wc[tid >> 5] = __popc(bal); }
    }
    __syncthreads();
    if (tid < 64) {
        int wd = tid >> 5;
        int base = (wd == 1) ? s_wc[0] : 0;
        if (m) s_idx[base + __popc(s_bal[wd] & ((1u << (tid & 31)) - 1u))] = lo + tid;
    }
    if (tid == 0) s_cnt = s_wc[0] + s_wc[1];
    __syncthreads();

    const int cnt = s_cnt;
    const float4* hp = (const float4*)(hidden + (size_t)b * SS * DD);

    float4 a0 = make_float4(0.f, 0.f, 0.f, 0.f);
    float4 a1 = make_float4(0.f, 0.f, 0.f, 0.f);
    float4 a2 = make_float4(0.f, 0.f, 0.f, 0.f);
    float4 a3 = make_float4(0.f, 0.f, 0.f, 0.f);

    int i = 0;
    for (; i + 8 <= cnt; i += 8) {
        float4 x[8];
        #pragma unroll
        for (int u = 0; u < 8; u++)
            x[u] = __ldcs(&hp[s_idx[i + u] * (DD / 4) + tid]);
        a0.x += x[0].x; a0.y += x[0].y; a0.z += x[0].z; a0.w += x[0].w;
        a1.x += x[1].x; a1.y += x[1].y; a1.z += x[1].z; a1.w += x[1].w;
        a2.x += x[2].x; a2.y += x[2].y; a2.z += x[2].z; a2.w += x[2].w;
        a3.x += x[3].x; a3.y += x[3].y; a3.z += x[3].z; a3.w += x[3].w;
        a0.x += x[4].x; a0.y += x[4].y; a0.z += x[4].z; a0.w += x[4].w;
        a1.x += x[5].x; a1.y += x[5].y; a1.z += x[5].z; a1.w += x[5].w;
        a2.x += x[6].x; a2.y += x[6].y; a2.z += x[6].z; a2.w += x[6].w;
        a3.x += x[7].x; a3.y += x[7].y; a3.z += x[7].z; a3.w += x[7].w;
    }
    for (; i < cnt; i++) {
        float4 x0 = __ldcs(&hp[s_idx[i] * (DD / 4) + tid]);
        a0.x += x0.x; a0.y += x0.y; a0.z += x0.z; a0.w += x0.w;
    }

    float4 r;
    r.x = (a0.x + a1.x) + (a2.x + a3.x);
    r.y = (a0.y + a1.y) + (a2.y + a3.y);
    r.z = (a0.z + a1.z) + (a2.z + a3.z);
    r.w = (a0.w + a1.w) + (a2.w + a3.w);
    ((float4*)(g_vp + (size_t)(half * BB + b) * DD))[tid] = r;
}

// ---------------------------------------------------------------------------
// Kernel B: full MLP per 8-row block. 128 blocks x 256 threads.
// GEMM1 uses a 16-deep software-pipelined W1 register stream.
// ---------------------------------------------------------------------------
__global__ void __launch_bounds__(256) mlp_kernel(
    const float* __restrict__ W1, const float* __restrict__ b1,
    const float* __restrict__ W2, const float* __restrict__ b2,
    const float* __restrict__ W3, const float* __restrict__ b3,
    float* __restrict__ out)
{
    __shared__ float vs[DD * ROWS];       // [k][r], r fast
    __shared__ float h1s[ROWS][H1];
    __shared__ float h2s[ROWS][H2];

    const int tid = threadIdx.x;
    const int r0  = blockIdx.x * ROWS;
    const float inv127 = 1.0f / 127.0f;

    // Stage v rows: v = (partial0 + partial1) / 127
    #pragma unroll
    for (int r = 0; r < ROWS; r++) {
        const float4* p0 = (const float4*)(g_vp + (size_t)(r0 + r) * DD);
        const float4* p1 = (const float4*)(g_vp + (size_t)(BB + r0 + r) * DD);
        if (tid < DD / 4) {
            float4 u = __ldg(&p0[tid]);
            float4 w = __ldg(&p1[tid]);
            float* dst = &vs[(tid * 4) * ROWS + r];
            dst[0 * ROWS] = (u.x + w.x) * inv127;
            dst[1 * ROWS] = (u.y + w.y) * inv127;
            dst[2 * ROWS] = (u.z + w.z) * inv127;
            dst[3 * ROWS] = (u.w + w.w) * inv127;
        }
    }
    __syncthreads();

    // GEMM1: acc[r] = sum_k v[r][k] * W1[k][tid], 16-deep pipelined W1 loads
    float acc[ROWS];
    #pragma unroll
    for (int r = 0; r < ROWS; r++) acc[r] = 0.0f;

    const float* w1c = W1 + tid;
    #pragma unroll 1
    for (int k0 = 0; k0 < DD; k0 += 16) {
        float w[16];
        #pragma unroll
        for (int u = 0; u < 16; u++)
            w[u] = __ldg(&w1c[(k0 + u) * H1]);
        #pragma unroll
        for (int u = 0; u < 16; u++) {
            float4 va = *(const float4*)&vs[(k0 + u) * ROWS];
            float4 vb = *(const float4*)&vs[(k0 + u) * ROWS + 4];
            acc[0] = fmaf(va.x, w[u], acc[0]);
            acc[1] = fmaf(va.y, w[u], acc[1]);
            acc[2] = fmaf(va.z, w[u], acc[2]);
            acc[3] = fmaf(va.w, w[u], acc[3]);
            acc[4] = fmaf(vb.x, w[u], acc[4]);
            acc[5] = fmaf(vb.y, w[u], acc[5]);
            acc[6] = fmaf(vb.z, w[u], acc[6]);
            acc[7] = fmaf(vb.w, w[u], acc[7]);
        }
    }
    {
        float bias = __ldg(&b1[tid]);
        #pragma unroll
        for (int r = 0; r < ROWS; r++)
            h1s[r][tid] = fmaxf(acc[r] + bias, 0.0f);
    }
    __syncthreads();

    // GEMM2: thread t -> col j = t&63, rows rr and rr+4 where rr = t>>6
    {
        const int j  = tid & (H2 - 1);
        const int rr = tid >> 6;           // 0..3
        float s0 = 0.0f, s1 = 0.0f;
        #pragma unroll 8
        for (int k = 0; k < H1; k++) {
            float w = __ldg(&W2[k * H2 + j]);
            s0 = fmaf(h1s[rr][k],     w, s0);
            s1 = fmaf(h1s[rr + 4][k], w, s1);
        }
        float bias = __ldg(&b2[j]);
        h2s[rr][j]     = fmaxf(s0 + bias, 0.0f);
        h2s[rr + 4][j] = fmaxf(s1 + bias, 0.0f);
    }
    __syncthreads();

    // GEMM3: 16 outputs (8 rows x 2 logits)
    if (tid < ROWS * OUTC) {
        const int r = tid >> 1;
        const int j = tid & 1;
        float s = __ldg(&b3[j]);
        #pragma unroll 8
        for (int c = 0; c < H2; c++)
            s = fmaf(h2s[r][c], __ldg(&W3[c * OUTC + j]), s);
        out[(size_t)(r0 + r) * OUTC + j] = s;
    }
}

// ---------------------------------------------------------------------------
extern "C" void kernel_launch(void* const* d_in, const int* in_sizes, int n_in,
                              void* d_out, int out_size) {
    const float* hidden = (const float*)d_in[0];
    const void*  mask   = d_in[1];
    const float* W1 = (const float*)d_in[2];
    const float* b1 = (const float*)d_in[3];
    const float* W2 = (const float*)d_in[4];
    const float* b2 = (const float*)d_in[5];
    const float* W3 = (const float*)d_in[6];
    const float* b3 = (const float*)d_in[7];
    float* out = (float*)d_out;

    detect_mask_kernel<<<1, 256>>>((const unsigned int*)mask);
    reduce_kernel<<<2 * BB, 192>>>(hidden, mask);
    mlp_kernel<<<BB / ROWS, 256>>>(W1, b1, W2, b2, W3, b3, out);
}

// round 3
// speedup vs baseline: 2.4764x; 1.0036x over previous
#include <cuda_runtime.h>
#include <cuda_bf16.h>

// Problem constants (SpectralClassifier: B=1024, S=128, D=768)
#define BB 1024
#define SS 128
#define DD 768
#define H1 256
#define H2 64
#define OUTC 2
#define ROWS 8
#define QTRS 4
#define DET_WORDS 256    // per-block detection sample (1KB, L2-broadcast)

// Scratch (no cudaMalloc allowed).
// g_vp holds UNSCALED partial sums: [quarter][b][d]
__device__ float g_vp[QTRS * BB * DD];

// packed dual-fp32 FMA (sm_100+): d = a*b + c elementwise on 2 lanes
#define FMA_F32X2(d, a, b, c) \
    asm("fma.rn.f32x2 %0, %1, %2, %3;" : "=l"(d) : "l"(a), "l"(b), "l"(c))

__device__ __forceinline__ bool mask_at(const void* mask, int idx, int mode) {
    if (mode == 0) return ((const int*)mask)[idx] != 0;
    if (mode == 1) return ((const float*)mask)[idx] != 0.0f;
    return ((const unsigned char*)mask)[idx] != 0;
}

// ---------------------------------------------------------------------------
// Kernel A: partial masked seq-sums with inline mask-dtype detection.
// 4096 blocks: blockIdx.x = b*4 + q. Quarter q covers s in [max(1,32q), 32(q+1)).
// 192 threads, one float4 column each. Warp-0 ballot compaction,
// 8-deep LDG pipeline, streaming loads. Unscaled partials -> g_vp.
// ---------------------------------------------------------------------------
__global__ void __launch_bounds__(192) reduce_kernel(
    const float* __restrict__ hidden, const void* __restrict__ mask)
{
    __shared__ int s_idx[32];
    __shared__ int s_cnt;
    __shared__ int s_mode;

    const int b   = blockIdx.x >> 2;
    const int q   = blockIdx.x & 3;
    const int lo  = (q == 0) ? 1 : (q * 32);
    const int nrows = (q == 0) ? 31 : 32;
    const int tid = threadIdx.x;

    // --- inline dtype detection on a 256-word sample (warps 0..5 share) ---
    {
        int bad_i = 0, bad_f = 0;
        const uint4* w4 = (const uint4*)mask;
        for (int i = tid; i < DET_WORDS / 4; i += 192) {
            uint4 v = __ldg(&w4[i]);
            unsigned arr[4] = {v.x, v.y, v.z, v.w};
            #pragma unroll
            for (int j = 0; j < 4; j++) {
                unsigned u = arr[j];
                if (u > 1u) bad_i = 1;
                float f = __uint_as_float(u);
                if (!(f == 0.0f || f == 1.0f)) bad_f = 1;
            }
        }
        bad_i = __any_sync(0xffffffffu, bad_i);
        bad_f = __any_sync(0xffffffffu, bad_f);
        if (tid == 0) s_mode = 0;
        __syncthreads();
        if ((tid & 31) == 0) {
            int mode = (!bad_i) ? 0 : ((!bad_f) ? 1 : 2);
            atomicMax(&s_mode, mode);   // all warps agree; max is harmless
        }
        __syncthreads();
    }
    const int mode = s_mode;

    // --- warp 0: mask ballot compaction for this quarter ---
    if (tid < 32) {
        bool m = (tid < nrows) && mask_at(mask, b * SS + lo + tid, mode);
        unsigned bal = __ballot_sync(0xffffffffu, m);
        if (m) s_idx[__popc(bal & ((1u << tid) - 1u))] = lo + tid;
        if (tid == 0) s_cnt = __popc(bal);
    }
    __syncthreads();

    const int cnt = s_cnt;
    const float4* hp = (const float4*)(hidden + (size_t)b * SS * DD);

    float4 a0 = make_float4(0.f, 0.f, 0.f, 0.f);
    float4 a1 = make_float4(0.f, 0.f, 0.f, 0.f);
    float4 a2 = make_float4(0.f, 0.f, 0.f, 0.f);
    float4 a3 = make_float4(0.f, 0.f, 0.f, 0.f);

    int i = 0;
    for (; i + 8 <= cnt; i += 8) {
        float4 x[8];
        #pragma unroll
        for (int u = 0; u < 8; u++)
            x[u] = __ldcs(&hp[s_idx[i + u] * (DD / 4) + tid]);
        a0.x += x[0].x; a0.y += x[0].y; a0.z += x[0].z; a0.w += x[0].w;
        a1.x += x[1].x; a1.y += x[1].y; a1.z += x[1].z; a1.w += x[1].w;
        a2.x += x[2].x; a2.y += x[2].y; a2.z += x[2].z; a2.w += x[2].w;
        a3.x += x[3].x; a3.y += x[3].y; a3.z += x[3].z; a3.w += x[3].w;
        a0.x += x[4].x; a0.y += x[4].y; a0.z += x[4].z; a0.w += x[4].w;
        a1.x += x[5].x; a1.y += x[5].y; a1.z += x[5].z; a1.w += x[5].w;
        a2.x += x[6].x; a2.y += x[6].y; a2.z += x[6].z; a2.w += x[6].w;
        a3.x += x[7].x; a3.y += x[7].y; a3.z += x[7].z; a3.w += x[7].w;
    }
    for (; i < cnt; i++) {
        float4 x0 = __ldcs(&hp[s_idx[i] * (DD / 4) + tid]);
        a0.x += x0.x; a0.y += x0.y; a0.z += x0.z; a0.w += x0.w;
    }

    float4 r;
    r.x = (a0.x + a1.x) + (a2.x + a3.x);
    r.y = (a0.y + a1.y) + (a2.y + a3.y);
    r.z = (a0.z + a1.z) + (a2.z + a3.z);
    r.w = (a0.w + a1.w) + (a2.w + a3.w);
    ((float4*)(g_vp + (size_t)(q * BB + b) * DD))[tid] = r;
}

// ---------------------------------------------------------------------------
// Kernel B: full MLP per 8-row block. 128 blocks x 256 threads.
// GEMM1: 16-deep W1 register pipeline + packed fma.rn.f32x2 (4 FFMA2/k-step).
// ---------------------------------------------------------------------------
__global__ void __launch_bounds__(256) mlp_kernel(
    const float* __restrict__ W1, const float* __restrict__ b1,
    const float* __restrict__ W2, const float* __restrict__ b2,
    const float* __restrict__ W3, const float* __restrict__ b3,
    float* __restrict__ out)
{
    __shared__ float vs[DD * ROWS];       // [k][r], r fast
    __shared__ float h1s[ROWS][H1];
    __shared__ float h2s[ROWS][H2];

    const int tid = threadIdx.x;
    const int r0  = blockIdx.x * ROWS;
    const float inv127 = 1.0f / 127.0f;

    // Stage v rows: v = (sum of 4 quarter partials) / 127, transposed [k][r]
    #pragma unroll
    for (int r = 0; r < ROWS; r++) {
        if (tid < DD / 4) {
            const float4* p0 = (const float4*)(g_vp + (size_t)(0 * BB + r0 + r) * DD);
            const float4* p1 = (const float4*)(g_vp + (size_t)(1 * BB + r0 + r) * DD);
            const float4* p2 = (const float4*)(g_vp + (size_t)(2 * BB + r0 + r) * DD);
            const float4* p3 = (const float4*)(g_vp + (size_t)(3 * BB + r0 + r) * DD);
            float4 u0 = __ldg(&p0[tid]);
            float4 u1 = __ldg(&p1[tid]);
            float4 u2 = __ldg(&p2[tid]);
            float4 u3 = __ldg(&p3[tid]);
            float* dst = &vs[(tid * 4) * ROWS + r];
            dst[0 * ROWS] = ((u0.x + u1.x) + (u2.x + u3.x)) * inv127;
            dst[1 * ROWS] = ((u0.y + u1.y) + (u2.y + u3.y)) * inv127;
            dst[2 * ROWS] = ((u0.z + u1.z) + (u2.z + u3.z)) * inv127;
            dst[3 * ROWS] = ((u0.w + u1.w) + (u2.w + u3.w)) * inv127;
        }
    }
    __syncthreads();

    // GEMM1: acc[r] = sum_k v[r][k] * W1[k][tid]
    // Packed accumulators: accp[j] holds rows (2j, 2j+1)
    unsigned long long accp[4] = {0ull, 0ull, 0ull, 0ull};

    const float* w1c = W1 + tid;
    #pragma unroll 1
    for (int k0 = 0; k0 < DD; k0 += 16) {
        float w[16];
        #pragma unroll
        for (int u = 0; u < 16; u++)
            w[u] = __ldg(&w1c[(k0 + u) * H1]);
        #pragma unroll
        for (int u = 0; u < 16; u++) {
            unsigned long long ww;
            asm("mov.b64 %0, {%1, %1};" : "=l"(ww) : "f"(w[u]));
            const ulonglong2 va = *(const ulonglong2*)&vs[(k0 + u) * ROWS];
            const ulonglong2 vb = *(const ulonglong2*)&vs[(k0 + u) * ROWS + 4];
            FMA_F32X2(accp[0], va.x, ww, accp[0]);
            FMA_F32X2(accp[1], va.y, ww, accp[1]);
            FMA_F32X2(accp[2], vb.x, ww, accp[2]);
            FMA_F32X2(accp[3], vb.y, ww, accp[3]);
        }
    }
    {
        float bias = __ldg(&b1[tid]);
        #pragma unroll
        for (int j = 0; j < 4; j++) {
            float lo, hi;
            asm("mov.b64 {%0, %1}, %2;" : "=f"(lo), "=f"(hi) : "l"(accp[j]));
            h1s[2 * j][tid]     = fmaxf(lo + bias, 0.0f);
            h1s[2 * j + 1][tid] = fmaxf(hi + bias, 0.0f);
        }
    }
    __syncthreads();

    // GEMM2: thread t -> col j = t&63, rows rr and rr+4 where rr = t>>6
    {
        const int j  = tid & (H2 - 1);
        const int rr = tid >> 6;           // 0..3
        float s0 = 0.0f, s1 = 0.0f;
        #pragma unroll 8
        for (int k = 0; k < H1; k++) {
            float w = __ldg(&W2[k * H2 + j]);
            s0 = fmaf(h1s[rr][k],     w, s0);
            s1 = fmaf(h1s[rr + 4][k], w, s1);
        }
        float bias = __ldg(&b2[j]);
        h2s[rr][j]     = fmaxf(s0 + bias, 0.0f);
        h2s[rr + 4][j] = fmaxf(s1 + bias, 0.0f);
    }
    __syncthreads();

    // GEMM3: 16 outputs (8 rows x 2 logits)
    if (tid < ROWS * OUTC) {
        const int r = tid >> 1;
        const int j = tid & 1;
        float s = __ldg(&b3[j]);
        #pragma unroll 8
        for (int c = 0; c < H2; c++)
            s = fmaf(h2s[r][c], __ldg(&W3[c * OUTC + j]), s);
        out[(size_t)(r0 + r) * OUTC + j] = s;
    }
}

// ---------------------------------------------------------------------------
extern "C" void kernel_launch(void* const* d_in, const int* in_sizes, int n_in,
                              void* d_out, int out_size) {
    const float* hidden = (const float*)d_in[0];
    const void*  mask   = d_in[1];
    const float* W1 = (const float*)d_in[2];
    const float* b1 = (const float*)d_in[3];
    const float* W2 = (const float*)d_in[4];
    const float* b2 = (const float*)d_in[5];
    const float* W3 = (const float*)d_in[6];
    const float* b3 = (const float*)d_in[7];
    float* out = (float*)d_out;

    reduce_kernel<<<QTRS * BB, 192>>>(hidden, mask);
    mlp_kernel<<<BB / ROWS, 256>>>(W1, b1, W2, b2, W3, b3, out);
}

// round 4
// speedup vs baseline: 2.6063x; 1.0524x over previous
#include <cuda_runtime.h>
#include <cuda_bf16.h>

// Problem constants (SpectralClassifier: B=1024, S=128, D=768)
#define BB 1024
#define SS 128
#define DD 768
#define H1 256
#define H2 64
#define OUTC 2
#define ROWS 8
#define QTRS 4
#define DET_WORDS 256    // per-block detection sample (1KB, L2-broadcast)
#define KC 32            // k-chunk for W1 smem tiles
#define NCHUNK (DD / KC) // 24

// Scratch (no cudaMalloc allowed).
// g_vp holds UNSCALED partial sums: [quarter][b][d]
__device__ float g_vp[QTRS * BB * DD];

// packed dual-fp32 FMA (sm_100+)
#define FMA_F32X2(d, a, b, c) \
    asm("fma.rn.f32x2 %0, %1, %2, %3;" : "=l"(d) : "l"(a), "l"(b), "l"(c))

__device__ __forceinline__ void cpasync16(float* smem_dst, const float* gsrc) {
    unsigned saddr = (unsigned)__cvta_generic_to_shared(smem_dst);
    asm volatile("cp.async.cg.shared.global [%0], [%1], 16;" :: "r"(saddr), "l"(gsrc) : "memory");
}
#define CP_COMMIT()  asm volatile("cp.async.commit_group;" ::: "memory")
#define CP_WAIT(n)   asm volatile("cp.async.wait_group %0;" :: "n"(n) : "memory")

__device__ __forceinline__ bool mask_at(const void* mask, int idx, int mode) {
    if (mode == 0) return ((const int*)mask)[idx] != 0;
    if (mode == 1) return ((const float*)mask)[idx] != 0.0f;
    return ((const unsigned char*)mask)[idx] != 0;
}

// ---------------------------------------------------------------------------
// Kernel A: partial masked seq-sums with inline mask-dtype detection.
// 4096 blocks: blockIdx.x = b*4 + q. Quarter q covers s in [max(1,32q), 32(q+1)).
// ---------------------------------------------------------------------------
__global__ void __launch_bounds__(192) reduce_kernel(
    const float* __restrict__ hidden, const void* __restrict__ mask)
{
    __shared__ int s_idx[32];
    __shared__ int s_cnt;
    __shared__ int s_mode;

    const int b   = blockIdx.x >> 2;
    const int q   = blockIdx.x & 3;
    const int lo  = (q == 0) ? 1 : (q * 32);
    const int nrows = (q == 0) ? 31 : 32;
    const int tid = threadIdx.x;

    // --- inline dtype detection on a 256-word sample ---
    {
        int bad_i = 0, bad_f = 0;
        const uint4* w4 = (const uint4*)mask;
        for (int i = tid; i < DET_WORDS / 4; i += 192) {
            uint4 v = __ldg(&w4[i]);
            unsigned arr[4] = {v.x, v.y, v.z, v.w};
            #pragma unroll
            for (int j = 0; j < 4; j++) {
                unsigned u = arr[j];
                if (u > 1u) bad_i = 1;
                float f = __uint_as_float(u);
                if (!(f == 0.0f || f == 1.0f)) bad_f = 1;
            }
        }
        bad_i = __any_sync(0xffffffffu, bad_i);
        bad_f = __any_sync(0xffffffffu, bad_f);
        if (tid == 0) s_mode = 0;
        __syncthreads();
        if ((tid & 31) == 0) {
            int mode = (!bad_i) ? 0 : ((!bad_f) ? 1 : 2);
            atomicMax(&s_mode, mode);
        }
        __syncthreads();
    }
    const int mode = s_mode;

    if (tid < 32) {
        bool m = (tid < nrows) && mask_at(mask, b * SS + lo + tid, mode);
        unsigned bal = __ballot_sync(0xffffffffu, m);
        if (m) s_idx[__popc(bal & ((1u << tid) - 1u))] = lo + tid;
        if (tid == 0) s_cnt = __popc(bal);
    }
    __syncthreads();

    const int cnt = s_cnt;
    const float4* hp = (const float4*)(hidden + (size_t)b * SS * DD);

    float4 a0 = make_float4(0.f, 0.f, 0.f, 0.f);
    float4 a1 = make_float4(0.f, 0.f, 0.f, 0.f);
    float4 a2 = make_float4(0.f, 0.f, 0.f, 0.f);
    float4 a3 = make_float4(0.f, 0.f, 0.f, 0.f);

    int i = 0;
    for (; i + 8 <= cnt; i += 8) {
        float4 x[8];
        #pragma unroll
        for (int u = 0; u < 8; u++)
            x[u] = __ldcs(&hp[s_idx[i + u] * (DD / 4) + tid]);
        a0.x += x[0].x; a0.y += x[0].y; a0.z += x[0].z; a0.w += x[0].w;
        a1.x += x[1].x; a1.y += x[1].y; a1.z += x[1].z; a1.w += x[1].w;
        a2.x += x[2].x; a2.y += x[2].y; a2.z += x[2].z; a2.w += x[2].w;
        a3.x += x[3].x; a3.y += x[3].y; a3.z += x[3].z; a3.w += x[3].w;
        a0.x += x[4].x; a0.y += x[4].y; a0.z += x[4].z; a0.w += x[4].w;
        a1.x += x[5].x; a1.y += x[5].y; a1.z += x[5].z; a1.w += x[5].w;
        a2.x += x[6].x; a2.y += x[6].y; a2.z += x[6].z; a2.w += x[6].w;
        a3.x += x[7].x; a3.y += x[7].y; a3.z += x[7].z; a3.w += x[7].w;
    }
    for (; i < cnt; i++) {
        float4 x0 = __ldcs(&hp[s_idx[i] * (DD / 4) + tid]);
        a0.x += x0.x; a0.y += x0.y; a0.z += x0.z; a0.w += x0.w;
    }

    float4 r;
    r.x = (a0.x + a1.x) + (a2.x + a3.x);
    r.y = (a0.y + a1.y) + (a2.y + a3.y);
    r.z = (a0.z + a1.z) + (a2.z + a3.z);
    r.w = (a0.w + a1.w) + (a2.w + a3.w);
    ((float4*)(g_vp + (size_t)(q * BB + b) * DD))[tid] = r;
}

// ---------------------------------------------------------------------------
// Kernel B: full MLP per 8-row block. 128 blocks x 256 threads.
// GEMM1: triple-buffered cp.async W1 tiles (32x256 = 32KB each) + fma.rn.f32x2.
// W2 (64KB) staged via cp.async overlapping the GEMM1 mainloop.
// Dynamic smem layout (floats):
//   sW1[3][KC*H1]  : 0      .. 24576
//   vs[DD*ROWS]    : 24576  .. 30720
//   h1s[ROWS][H1]  : 30720  .. 32768
//   sW2[H1*H2]     : 32768  .. 49152
//   h2s[ROWS][H2]  : 49152  .. 49664
// ---------------------------------------------------------------------------
#define SMEM_FLOATS 49664
#define OFF_W1  0
#define OFF_VS  24576
#define OFF_H1  30720
#define OFF_W2  32768
#define OFF_H2  49152

__global__ void __launch_bounds__(256) mlp_kernel(
    const float* __restrict__ W1, const float* __restrict__ b1,
    const float* __restrict__ W2, const float* __restrict__ b2,
    const float* __restrict__ W3, const float* __restrict__ b3,
    float* __restrict__ out)
{
    extern __shared__ float smf[];
    float* sW1 = smf + OFF_W1;
    float* vs  = smf + OFF_VS;
    float* h1s = smf + OFF_H1;
    float* sW2 = smf + OFF_W2;
    float* h2s = smf + OFF_H2;

    const int tid = threadIdx.x;
    const int r0  = blockIdx.x * ROWS;
    const float inv127 = 1.0f / 127.0f;

    // --- Prologue: async-prefetch chunk0, chunk1 (G0, G1), then W2 (G2) ---
    #pragma unroll
    for (int i = 0; i < KC * H1 / 4; i += 256)
        cpasync16(&sW1[0 * KC * H1 + (i + tid) * 4], &W1[0 * KC * H1 + (i + tid) * 4]);
    CP_COMMIT();
    #pragma unroll
    for (int i = 0; i < KC * H1 / 4; i += 256)
        cpasync16(&sW1[1 * KC * H1 + (i + tid) * 4], &W1[1 * KC * H1 + (i + tid) * 4]);
    CP_COMMIT();
    #pragma unroll
    for (int i = 0; i < H1 * H2 / 4; i += 256)
        cpasync16(&sW2[(i + tid) * 4], &W2[(i + tid) * 4]);
    CP_COMMIT();

    // --- Stage v rows while cp.asyncs fly: v = (sum of 4 partials)/127, [k][r] ---
    #pragma unroll
    for (int ii = 0; ii < 6; ii++) {
        int idx = ii * 256 + tid;          // 0..1535, covers 8 rows x 192 float4
        int r  = idx / (DD / 4);
        int c4 = idx % (DD / 4);
        const float4* p0 = (const float4*)(g_vp + (size_t)(0 * BB + r0 + r) * DD);
        const float4* p1 = (const float4*)(g_vp + (size_t)(1 * BB + r0 + r) * DD);
        const float4* p2 = (const float4*)(g_vp + (size_t)(2 * BB + r0 + r) * DD);
        const float4* p3 = (const float4*)(g_vp + (size_t)(3 * BB + r0 + r) * DD);
        float4 u0 = __ldg(&p0[c4]);
        float4 u1 = __ldg(&p1[c4]);
        float4 u2 = __ldg(&p2[c4]);
        float4 u3 = __ldg(&p3[c4]);
        float* dst = &vs[(c4 * 4) * ROWS + r];
        dst[0 * ROWS] = ((u0.x + u1.x) + (u2.x + u3.x)) * inv127;
        dst[1 * ROWS] = ((u0.y + u1.y) + (u2.y + u3.y)) * inv127;
        dst[2 * ROWS] = ((u0.z + u1.z) + (u2.z + u3.z)) * inv127;
        dst[3 * ROWS] = ((u0.w + u1.w) + (u2.w + u3.w)) * inv127;
    }

    // --- GEMM1 mainloop: triple-buffered chunks of KC k-steps ---
    unsigned long long accp[4] = {0ull, 0ull, 0ull, 0ull};

    #pragma unroll 1
    for (int c = 0; c < NCHUNK; c++) {
        if (c < NCHUNK - 2) {
            const int cc = c + 2;
            float* dstb = &sW1[(cc % 3) * KC * H1];
            const float* srcb = &W1[cc * KC * H1];
            #pragma unroll
            for (int i = 0; i < KC * H1 / 4; i += 256)
                cpasync16(&dstb[(i + tid) * 4], &srcb[(i + tid) * 4]);
            CP_COMMIT();
            CP_WAIT(2);
        } else if (c == NCHUNK - 2) {
            CP_WAIT(1);
        } else {
            CP_WAIT(0);
        }
        __syncthreads();

        const float* wbuf = &sW1[(c % 3) * KC * H1];
        const float* vk   = &vs[c * KC * ROWS];
        #pragma unroll
        for (int kk = 0; kk < KC; kk++) {
            float w = wbuf[kk * H1 + tid];
            unsigned long long ww;
            asm("mov.b64 %0, {%1, %1};" : "=l"(ww) : "f"(w));
            const ulonglong2 va = *(const ulonglong2*)&vk[kk * ROWS];
            const ulonglong2 vb = *(const ulonglong2*)&vk[kk * ROWS + 4];
            FMA_F32X2(accp[0], va.x, ww, accp[0]);
            FMA_F32X2(accp[1], va.y, ww, accp[1]);
            FMA_F32X2(accp[2], vb.x, ww, accp[2]);
            FMA_F32X2(accp[3], vb.y, ww, accp[3]);
        }
    }
    {
        float bias = __ldg(&b1[tid]);
        #pragma unroll
        for (int j = 0; j < 4; j++) {
            float lo, hi;
            asm("mov.b64 {%0, %1}, %2;" : "=f"(lo), "=f"(hi) : "l"(accp[j]));
            h1s[(2 * j) * H1 + tid]     = fmaxf(lo + bias, 0.0f);
            h1s[(2 * j + 1) * H1 + tid] = fmaxf(hi + bias, 0.0f);
        }
    }
    __syncthreads();

    // --- GEMM2 (from smem): thread t -> col j = t&63, rows rr and rr+4 ---
    {
        const int j  = tid & (H2 - 1);
        const int rr = tid >> 6;           // 0..3
        float s0 = 0.0f, s1 = 0.0f;
        #pragma unroll 16
        for (int k = 0; k < H1; k++) {
            float w = sW2[k * H2 + j];
            s0 = fmaf(h1s[rr * H1 + k],       w, s0);
            s1 = fmaf(h1s[(rr + 4) * H1 + k], w, s1);
        }
        float bias = __ldg(&b2[j]);
        h2s[rr * H2 + j]       = fmaxf(s0 + bias, 0.0f);
        h2s[(rr + 4) * H2 + j] = fmaxf(s1 + bias, 0.0f);
    }
    __syncthreads();

    // --- GEMM3: 16 outputs (8 rows x 2 logits) ---
    if (tid < ROWS * OUTC) {
        const int r = tid >> 1;
        const int j = tid & 1;
        float s = __ldg(&b3[j]);
        #pragma unroll 8
        for (int c = 0; c < H2; c++)
            s = fmaf(h2s[r * H2 + c], __ldg(&W3[c * OUTC + j]), s);
        out[(size_t)(r0 + r) * OUTC + j] = s;
    }
}

// ---------------------------------------------------------------------------
extern "C" void kernel_launch(void* const* d_in, const int* in_sizes, int n_in,
                              void* d_out, int out_size) {
    const float* hidden = (const float*)d_in[0];
    const void*  mask   = d_in[1];
    const float* W1 = (const float*)d_in[2];
    const float* b1 = (const float*)d_in[3];
    const float* W2 = (const float*)d_in[4];
    const float* b2 = (const float*)d_in[5];
    const float* W3 = (const float*)d_in[6];
    const float* b3 = (const float*)d_in[7];
    float* out = (float*)d_out;

    static int smem_set = 0;
    if (!smem_set) {
        cudaFuncSetAttribute(mlp_kernel,
                             cudaFuncAttributeMaxDynamicSharedMemorySize,
                             SMEM_FLOATS * sizeof(float));
        smem_set = 1;
    }

    reduce_kernel<<<QTRS * BB, 192>>>(hidden, mask);
    mlp_kernel<<<BB / ROWS, 256, SMEM_FLOATS * sizeof(float)>>>(
        W1, b1, W2, b2, W3, b3, out);
}